// round 1
// baseline (speedup 1.0000x reference)
#include <cuda_runtime.h>
#include <math.h>

#define MAXN 131072

// ---------------- device scratch (static globals; no allocation) ----------------
__device__ float g_NH[MAXN * 128];     // new_h pre-faction        (64 MB)
__device__ float g_OUT[MAXN * 64];     // out = a - g              (32 MB)
__device__ float g_T[MAXN];            // tension
__device__ float g_XA1[128];           // ba1 + x @ Wa1[:, :64].T
__device__ float g_XG1[128];           // bg1 + x @ Wg1[:, :64].T
__device__ float g_WihP[384 * 68];     // W_ih repacked, rows padded 65 -> 68 (zeros)
__device__ float g_FSUM[8 * 128];      // faction column sums of new_h
__device__ float g_FM[8 * 128];        // faction means
__device__ float g_GO[128];            // global mean of faction means
__device__ float g_tsum;
__device__ unsigned int g_tmaxbits;    // t >= 0 so uint compare == float compare
__device__ float g_sumexp;
__device__ float g_num[64];            // softmax-weighted sum numerator

// ---------------- helpers ----------------
__device__ __forceinline__ float dot4(float4 a, float4 b) {
    return a.x * b.x + a.y * b.y + a.z * b.z + a.w * b.w;
}
// swizzled smem word index, 128-wide rows (row stride 128 words, xor-swizzle by r&7)
__device__ __forceinline__ int sidx(int r, int k) {
    return (r << 7) + ((((k >> 2) ^ (r & 7)) << 2) | (k & 3));
}
// swizzled smem word index, 96-word rows (68 words used, padded for swizzle range)
__device__ __forceinline__ int midx(int r, int k) {
    return r * 96 + ((((k >> 2) ^ (r & 7)) << 2) | (k & 3));
}
__device__ __forceinline__ float sigmf(float x) { return 1.f / (1.f + expf(-x)); }

// ---------------- prologue: fold x into layer-1, repack W_ih, zero accumulators ----------------
__global__ void k_pre(const float* __restrict__ x,
                      const float* __restrict__ Wa1, const float* __restrict__ ba1,
                      const float* __restrict__ Wg1, const float* __restrict__ bg1,
                      const float* __restrict__ W_ih) {
    int t = threadIdx.x;
    if (t < 128) {
        float a = ba1[t], g = bg1[t];
        for (int k = 0; k < 64; ++k) {
            float xv = x[k];
            a += xv * Wa1[t * 192 + k];
            g += xv * Wg1[t * 192 + k];
        }
        g_XA1[t] = a;
        g_XG1[t] = g;
    }
    for (int e = t; e < 384 * 68; e += 256) {
        int j = e / 68, k = e % 68;
        g_WihP[e] = (k < 65) ? W_ih[j * 65 + k] : 0.f;
    }
    for (int e = t; e < 8 * 128; e += 256) g_FSUM[e] = 0.f;
    if (t < 64) g_num[t] = 0.f;
    if (t == 0) { g_tsum = 0.f; g_tmaxbits = 0u; g_sumexp = 0.f; }
}

// ---------------- main per-cell kernel: MLPs + GRU + partial reductions ----------------
// 64 rows per block, 256 threads. smem: sh[64x128] (h), shd[64x128] (hidden / new_h),
// smi[64x96] (out + tension, 68 words used). All float4-swizzled.
__global__ __launch_bounds__(256, 2) void k_main(
    const float* __restrict__ hiddens, const int* __restrict__ aidx,
    const float* __restrict__ Wa1, const float* __restrict__ Wa2, const float* __restrict__ ba2,
    const float* __restrict__ Wg1, const float* __restrict__ Wg2, const float* __restrict__ bg2,
    const float* __restrict__ Whh, const float* __restrict__ bih, const float* __restrict__ bhh,
    int n, int nf_fs, int fs)
{
    extern __shared__ float sm[];
    float* sh  = sm;            // 8192 words
    float* shd = sm + 8192;     // 8192 words
    float* smi = sm + 16384;    // 6144 words
    __shared__ int sg[64];

    const int t = threadIdx.x;
    const int w = t >> 5, lane = t & 31;
    const int i0 = blockIdx.x * 64;
    const int nr = min(64, n - i0);
    const int s0 = lane & 7;           // swizzle key; (lane+32)&7 == lane&7
    const int r0 = lane, r1 = lane + 32;

    if (t < 64) sg[t] = (t < nr) ? aidx[i0 + t] : 0;
    __syncthreads();

    // gather h rows (coalesced per row)
    for (int e = t; e < 64 * 128; e += 256) {
        int r = e >> 7, k = e & 127;
        sh[sidx(r, k)] = (r < nr) ? hiddens[sg[r] * 128 + k] : 0.f;
    }
    __syncthreads();

    // ---- a-path (path 0) and g-path (path 1) MLPs ----
    for (int path = 0; path < 2; ++path) {
        const float* W1 = path ? Wg1 : Wa1;
        const float* W2 = path ? Wg2 : Wa2;
        const float* b2 = path ? bg2 : ba2;
        const float* X1 = path ? g_XG1 : g_XA1;

        // layer 1: shd[r][j] = relu(X1[j] + sum_k sh[r][k] * W1[j*192 + 64 + k])
        for (int cc = w; cc < 32; cc += 8) {
            const int j0 = cc << 2;
            float4 a0 = make_float4(X1[j0], X1[j0 + 1], X1[j0 + 2], X1[j0 + 3]);
            float4 a1 = a0;
            const float4* w0 = (const float4*)(W1 + (j0 + 0) * 192 + 64);
            const float4* w1 = (const float4*)(W1 + (j0 + 1) * 192 + 64);
            const float4* w2 = (const float4*)(W1 + (j0 + 2) * 192 + 64);
            const float4* w3 = (const float4*)(W1 + (j0 + 3) * 192 + 64);
            const float4* h0p = (const float4*)sh + r0 * 32;
            const float4* h1p = (const float4*)sh + r1 * 32;
            #pragma unroll 8
            for (int k4 = 0; k4 < 32; ++k4) {
                float4 x0 = h0p[k4 ^ s0];
                float4 x1 = h1p[k4 ^ s0];
                float4 q0 = w0[k4], q1 = w1[k4], q2 = w2[k4], q3 = w3[k4];
                a0.x += dot4(x0, q0); a0.y += dot4(x0, q1);
                a0.z += dot4(x0, q2); a0.w += dot4(x0, q3);
                a1.x += dot4(x1, q0); a1.y += dot4(x1, q1);
                a1.z += dot4(x1, q2); a1.w += dot4(x1, q3);
            }
            a0.x = fmaxf(a0.x, 0.f); a0.y = fmaxf(a0.y, 0.f);
            a0.z = fmaxf(a0.z, 0.f); a0.w = fmaxf(a0.w, 0.f);
            a1.x = fmaxf(a1.x, 0.f); a1.y = fmaxf(a1.y, 0.f);
            a1.z = fmaxf(a1.z, 0.f); a1.w = fmaxf(a1.w, 0.f);
            ((float4*)shd)[r0 * 32 + (cc ^ s0)] = a0;
            ((float4*)shd)[r1 * 32 + (cc ^ s0)] = a1;
        }
        __syncthreads();

        // layer 2: smi[r][j] = a (path 0) ; smi[r][j] -= g (path 1)
        for (int cc = w; cc < 16; cc += 8) {
            const int j0 = cc << 2;
            float4 a0 = make_float4(b2[j0], b2[j0 + 1], b2[j0 + 2], b2[j0 + 3]);
            float4 a1 = a0;
            const float4* w0 = (const float4*)(W2 + (j0 + 0) * 128);
            const float4* w1 = (const float4*)(W2 + (j0 + 1) * 128);
            const float4* w2 = (const float4*)(W2 + (j0 + 2) * 128);
            const float4* w3 = (const float4*)(W2 + (j0 + 3) * 128);
            const float4* h0p = (const float4*)shd + r0 * 32;
            const float4* h1p = (const float4*)shd + r1 * 32;
            #pragma unroll 8
            for (int k4 = 0; k4 < 32; ++k4) {
                float4 x0 = h0p[k4 ^ s0];
                float4 x1 = h1p[k4 ^ s0];
                float4 q0 = w0[k4], q1 = w1[k4], q2 = w2[k4], q3 = w3[k4];
                a0.x += dot4(x0, q0); a0.y += dot4(x0, q1);
                a0.z += dot4(x0, q2); a0.w += dot4(x0, q3);
                a1.x += dot4(x1, q0); a1.y += dot4(x1, q1);
                a1.z += dot4(x1, q2); a1.w += dot4(x1, q3);
            }
            float4* d0 = (float4*)smi + r0 * 24 + (cc ^ s0);
            float4* d1 = (float4*)smi + r1 * 24 + (cc ^ s0);
            if (path == 0) {
                *d0 = a0; *d1 = a1;
            } else {
                float4 p0 = *d0, p1 = *d1;
                p0.x -= a0.x; p0.y -= a0.y; p0.z -= a0.z; p0.w -= a0.w;
                p1.x -= a1.x; p1.y -= a1.y; p1.z -= a1.z; p1.w -= a1.w;
                *d0 = p0; *d1 = p1;
            }
        }
        __syncthreads();
    }

    // ---- tension ----
    if (t < 64) {
        int r = t;
        float s = 0.f;
        for (int m = 0; m < 64; ++m) { float v = smi[midx(r, m)]; s += v * v; }
        float tn = s * (1.f / 64.f);
        smi[midx(r, 64)] = tn;
        smi[midx(r, 65)] = 0.f; smi[midx(r, 66)] = 0.f; smi[midx(r, 67)] = 0.f;
        if (r < nr) g_T[i0 + r] = tn;
    }
    __syncthreads();

    // store out, block-reduce tension sum/max
    for (int e = t; e < 64 * 64; e += 256) {
        int r = e >> 6, m = e & 63;
        if (r < nr) g_OUT[(i0 + r) * 64 + m] = smi[midx(r, m)];
    }
    if (t == 0) {
        float s = 0.f, mx = 0.f;
        for (int r = 0; r < nr; ++r) { float v = smi[midx(r, 64)]; s += v; mx = fmaxf(mx, v); }
        atomicAdd(&g_tsum, s);
        atomicMax(&g_tmaxbits, __float_as_uint(mx));
    }

    // ---- GRU: new_h[r][j] directly, 2 rows x 2 cols per warp-item ----
    for (int cc = w; cc < 64; cc += 8) {
        const int j0 = cc << 1;
        float br0 = bih[j0], br1 = bih[j0 + 1];
        float bz0 = bih[128 + j0], bz1 = bih[129 + j0];
        float bn0 = bih[256 + j0], bn1 = bih[257 + j0];
        float ir00 = br0, ir01 = br1, ir10 = br0, ir11 = br1;
        float iz00 = bz0, iz01 = bz1, iz10 = bz0, iz11 = bz1;
        float in00 = bn0, in01 = bn1, in10 = bn0, in11 = bn1;
        const float4* m0 = (const float4*)smi + r0 * 24;
        const float4* m1 = (const float4*)smi + r1 * 24;
        const float4* Wi = (const float4*)g_WihP;   // row stride 17 float4
        #pragma unroll 4
        for (int k4 = 0; k4 < 17; ++k4) {
            float4 x0 = m0[k4 ^ s0];
            float4 x1 = m1[k4 ^ s0];
            float4 q0 = Wi[(j0) * 17 + k4],        q1 = Wi[(j0 + 1) * 17 + k4];
            float4 q2 = Wi[(128 + j0) * 17 + k4],  q3 = Wi[(129 + j0) * 17 + k4];
            float4 q4 = Wi[(256 + j0) * 17 + k4],  q5 = Wi[(257 + j0) * 17 + k4];
            ir00 += dot4(x0, q0); ir01 += dot4(x0, q1);
            ir10 += dot4(x1, q0); ir11 += dot4(x1, q1);
            iz00 += dot4(x0, q2); iz01 += dot4(x0, q3);
            iz10 += dot4(x1, q2); iz11 += dot4(x1, q3);
            in00 += dot4(x0, q4); in01 += dot4(x0, q5);
            in10 += dot4(x1, q4); in11 += dot4(x1, q5);
        }
        float hr00 = bhh[j0], hr01 = bhh[j0 + 1], hr10 = hr00, hr11 = hr01;
        float hz00 = bhh[128 + j0], hz01 = bhh[129 + j0], hz10 = hz00, hz11 = hz01;
        float hn00 = bhh[256 + j0], hn01 = bhh[257 + j0], hn10 = hn00, hn11 = hn01;
        const float4* h0p = (const float4*)sh + r0 * 32;
        const float4* h1p = (const float4*)sh + r1 * 32;
        const float4* Wh = (const float4*)Whh;      // row stride 32 float4
        #pragma unroll 4
        for (int k4 = 0; k4 < 32; ++k4) {
            float4 x0 = h0p[k4 ^ s0];
            float4 x1 = h1p[k4 ^ s0];
            float4 q0 = Wh[(j0) * 32 + k4],        q1 = Wh[(j0 + 1) * 32 + k4];
            float4 q2 = Wh[(128 + j0) * 32 + k4],  q3 = Wh[(129 + j0) * 32 + k4];
            float4 q4 = Wh[(256 + j0) * 32 + k4],  q5 = Wh[(257 + j0) * 32 + k4];
            hr00 += dot4(x0, q0); hr01 += dot4(x0, q1);
            hr10 += dot4(x1, q0); hr11 += dot4(x1, q1);
            hz00 += dot4(x0, q2); hz01 += dot4(x0, q3);
            hz10 += dot4(x1, q2); hz11 += dot4(x1, q3);
            hn00 += dot4(x0, q4); hn01 += dot4(x0, q5);
            hn10 += dot4(x1, q4); hn11 += dot4(x1, q5);
        }
        {
            float rg = sigmf(ir00 + hr00), zg = sigmf(iz00 + hz00);
            float ng = tanhf(in00 + rg * hn00);
            float hv = sh[sidx(r0, j0)];
            shd[sidx(r0, j0)] = (1.f - zg) * ng + zg * hv;
        }
        {
            float rg = sigmf(ir01 + hr01), zg = sigmf(iz01 + hz01);
            float ng = tanhf(in01 + rg * hn01);
            float hv = sh[sidx(r0, j0 + 1)];
            shd[sidx(r0, j0 + 1)] = (1.f - zg) * ng + zg * hv;
        }
        {
            float rg = sigmf(ir10 + hr10), zg = sigmf(iz10 + hz10);
            float ng = tanhf(in10 + rg * hn10);
            float hv = sh[sidx(r1, j0)];
            shd[sidx(r1, j0)] = (1.f - zg) * ng + zg * hv;
        }
        {
            float rg = sigmf(ir11 + hr11), zg = sigmf(iz11 + hz11);
            float ng = tanhf(in11 + rg * hn11);
            float hv = sh[sidx(r1, j0 + 1)];
            shd[sidx(r1, j0 + 1)] = (1.f - zg) * ng + zg * hv;
        }
    }
    __syncthreads();

    // coalesced new_h store
    for (int e = t; e < 64 * 128; e += 256) {
        int r = e >> 7, k = e & 127;
        if (r < nr) g_NH[(i0 + r) * 128 + k] = shd[sidx(r, k)];
    }

    // faction column partial sums (handles a faction boundary inside the block)
    if (nf_fs > 0 && t < 128) {
        int j = t;
        float acc = 0.f;
        int curf = -1;
        for (int r = 0; r < nr; ++r) {
            int i = i0 + r;
            if (i >= nf_fs) break;
            int f = i / fs;
            if (f != curf) {
                if (curf >= 0) atomicAdd(&g_FSUM[curf * 128 + j], acc);
                curf = f; acc = 0.f;
            }
            acc += shd[sidx(r, j)];
        }
        if (curf >= 0) atomicAdd(&g_FSUM[curf * 128 + j], acc);
    }
}

// ---------------- faction means + mean tension ----------------
__global__ void k_fm(float* __restrict__ dout, int n, int n_f, int fs) {
    int j = threadIdx.x;   // 128 threads
    if (j == 0) dout[64] = g_tsum / (float)n;
    if (n_f >= 2) {
        float s = 0.f;
        float inv = 1.f / (float)fs;
        for (int f = 0; f < n_f; ++f) {
            float m = g_FSUM[f * 128 + j] * inv;
            g_FM[f * 128 + j] = m;
            s += m;
        }
        g_GO[j] = s / (float)n_f;
    }
}

// ---------------- softmax numerator / denominator ----------------
__global__ void k_soft(int n) {
    int t = threadIdx.x, w = t >> 5, lane = t & 31;
    int ib = blockIdx.x * 1024 + w * 128;
    float tmax = __uint_as_float(g_tmaxbits);
    float p0 = 0.f, p1 = 0.f, es = 0.f;
    for (int rr = 0; rr < 128; ++rr) {
        int i = ib + rr;
        if (i >= n) break;
        float e = expf(g_T[i] - tmax);
        if (lane == 0) es += e;
        p0 += e * g_OUT[i * 64 + lane];
        p1 += e * g_OUT[i * 64 + 32 + lane];
    }
    atomicAdd(&g_num[lane], p0);
    atomicAdd(&g_num[32 + lane], p1);
    if (lane == 0) atomicAdd(&g_sumexp, es);
}

// ---------------- faction sync/debate + scatter into output hiddens ----------------
__global__ void k_fin(float* __restrict__ dout, const int* __restrict__ aidx,
                      const int* __restrict__ step, int n, int nf_fs, int fs, int dc) {
    int t = threadIdx.x;
    int i = blockIdx.x * 2 + (t >> 7);
    int j = t & 127;
    if (i >= n) return;
    float v = g_NH[i * 128 + j];
    if (i < nf_fs) {
        int f = i / fs, l = i - f * fs;
        v = 0.85f * v + 0.15f * g_FM[f * 128 + j];
        if (*step > 5 && l < dc) v = 0.85f * v + 0.15f * g_GO[j];
    }
    dout[65 + aidx[i] * 128 + j] = v;
}

// ---------------- combined output ----------------
__global__ void k_comb(float* __restrict__ dout) {
    int m = threadIdx.x;  // 64 threads
    dout[m] = g_num[m] / g_sumexp;
}

// ---------------- launch ----------------
extern "C" void kernel_launch(void* const* d_in, const int* in_sizes, int n_in,
                              void* d_out, int out_size) {
    const float* x       = (const float*)d_in[0];
    const float* hiddens = (const float*)d_in[1];
    const float* Wa1     = (const float*)d_in[2];
    const float* ba1     = (const float*)d_in[3];
    const float* Wa2     = (const float*)d_in[4];
    const float* ba2     = (const float*)d_in[5];
    const float* Wg1     = (const float*)d_in[6];
    const float* bg1     = (const float*)d_in[7];
    const float* Wg2     = (const float*)d_in[8];
    const float* bg2     = (const float*)d_in[9];
    const float* W_ih    = (const float*)d_in[10];
    const float* W_hh    = (const float*)d_in[11];
    const float* b_ih    = (const float*)d_in[12];
    const float* b_hh    = (const float*)d_in[13];
    const int*   aidx    = (const int*)d_in[14];
    const int*   step    = (const int*)d_in[15];

    int n = in_sizes[14];
    int n_f = (n / 2 < 8) ? (n / 2) : 8;
    int fs = (n_f >= 2) ? (n / n_f) : 1;
    int nf_fs = (n_f >= 2) ? (n_f * fs) : 0;
    int dc = (fs / 4 > 1) ? (fs / 4) : 1;

    float* out = (float*)d_out;

    // pass-through copy of hiddens into the output; alive rows overwritten by k_fin
    cudaMemcpyAsync(out + 65, hiddens, (size_t)in_sizes[1] * sizeof(float),
                    cudaMemcpyDeviceToDevice, 0);

    k_pre<<<1, 256>>>(x, Wa1, ba1, Wg1, bg1, W_ih);

    const int smem_bytes = (8192 + 8192 + 6144) * 4;   // 90112 B
    cudaFuncSetAttribute(k_main, cudaFuncAttributeMaxDynamicSharedMemorySize, smem_bytes);
    k_main<<<(n + 63) / 64, 256, smem_bytes>>>(
        hiddens, aidx, Wa1, Wa2, ba2, Wg1, Wg2, bg2, W_hh, b_ih, b_hh,
        n, nf_fs, fs);

    k_fm<<<1, 128>>>(out, n, n_f, fs);
    k_soft<<<(n + 1023) / 1024, 256>>>(n);
    k_fin<<<(n + 1) / 2, 256>>>(out, aidx, step, n, nf_fs, fs, dc);
    k_comb<<<1, 64>>>(out);
}